// round 7
// baseline (speedup 1.0000x reference)
#include <cuda_runtime.h>
#include <cuda_fp16.h>

#define N_USERS 200000
#define N_ITEMS 100000
#define NNODES  300000
#define NE      5000000
#define BATCH   4096
#define NEPAD   (NE + 3 * NNODES + 16)
#define NB      ((NNODES + 1023) / 1024)

// ---------------- scratch (static device globals; no allocation) ----------------
__device__ int4   g_xa[(size_t)NNODES * 8];      // fp16 features ping (8 halves per int4)
__device__ int4   g_xb[(size_t)NNODES * 8];      // fp16 features pong
__device__ float4 g_l1f[(size_t)NNODES * 16];    // fp32 layer-1 rows (flagged only)
__device__ float4 g_l2f[(size_t)NNODES * 16];    // fp32 layer-2 rows (flagged only)
__device__ int    g_rowstart[NNODES];
__device__ int    g_counts[NNODES];
__device__ int    g_cursor[NNODES];
__device__ char   g_flag[NNODES];
__device__ unsigned long long g_ss[NB];          // lookback scan status: (sum<<2)|state
__device__ __align__(16) int2 g_edges[NEPAD];    // (col, half2(val,val) bits), row-sorted, 4-padded

// ---------------- 1: count (x4 unrolled) + E0 fp16 init + sample flags ----------------
__global__ void k_countinit(const int* __restrict__ rows,
                            const float* __restrict__ user_emb,
                            const float* __restrict__ item_emb,
                            const int* __restrict__ users,
                            const int* __restrict__ pos,
                            const int* __restrict__ neg) {
    int t = blockIdx.x * blockDim.x + threadIdx.x;
    if (t < NE / 4) {
        int4 r = __ldcs(&((const int4*)rows)[t]);
        atomicAdd(&g_counts[r.x], 1);            // result unused -> REDG (fire & forget)
        atomicAdd(&g_counts[r.y], 1);
        atomicAdd(&g_counts[r.z], 1);
        atomicAdd(&g_counts[r.w], 1);
    }
    if (t < NNODES * 8) {
        int node = t >> 3, k = t & 7;
        const float4* src = (node < N_USERS)
            ? (const float4*)user_emb + (size_t)node * 16
            : (const float4*)item_emb + (size_t)(node - N_USERS) * 16;
        float4 a = __ldcs(&src[2 * k]);
        float4 b = __ldcs(&src[2 * k + 1]);
        __half2 h0 = __floats2half2_rn(a.x, a.y);
        __half2 h1 = __floats2half2_rn(a.z, a.w);
        __half2 h2 = __floats2half2_rn(b.x, b.y);
        __half2 h3 = __floats2half2_rn(b.z, b.w);
        int4 o;
        o.x = *(int*)&h0; o.y = *(int*)&h1; o.z = *(int*)&h2; o.w = *(int*)&h3;
        g_xa[t] = o;
    }
    if (t < BATCH) {
        g_flag[users[t]] = 1;
        g_flag[N_USERS + pos[t]] = 1;
        g_flag[N_USERS + neg[t]] = 1;
    }
}

// ---------------- 2: single-pass decoupled-lookback scan of padded counts ----------------
__global__ void __launch_bounds__(1024) k_scanLB() {
    __shared__ int sh[1024];
    __shared__ int s_prefix;
    int tid = threadIdx.x, b = blockIdx.x;
    int i = b * 1024 + tid;
    int c = (i < NNODES) ? g_counts[i] : 0;
    int v = (c + 3) & ~3;                      // pad rows to multiple of 4 edges
    sh[tid] = v;
    __syncthreads();
    #pragma unroll
    for (int off = 1; off < 1024; off <<= 1) {
        int t = (tid >= off) ? sh[tid - off] : 0;
        __syncthreads();
        sh[tid] += t;
        __syncthreads();
    }
    int incl = sh[tid];
    int total = sh[1023];
    if (tid == 0) {
        if (b == 0) {
            atomicExch(&g_ss[0], ((unsigned long long)(unsigned)total << 2) | 2ull);
            s_prefix = 0;
        } else {
            atomicExch(&g_ss[b], ((unsigned long long)(unsigned)total << 2) | 1ull);
            int run = 0;
            for (int p = b - 1; ; p--) {
                unsigned long long s;
                do { s = atomicOr(&g_ss[p], 0ull); } while (!(s & 3ull));
                run += (int)(s >> 2);
                if ((s & 3ull) == 2ull) break;
            }
            atomicExch(&g_ss[b], ((unsigned long long)(unsigned)(run + total) << 2) | 2ull);
            s_prefix = run;
        }
    }
    __syncthreads();
    if (i < NNODES) {
        int excl = s_prefix + incl - v;
        g_rowstart[i] = excl;
        g_cursor[i]   = excl;
    }
}

// ---------------- 3: scatter (x4 unrolled, val pre-converted to half2) + padding ------
__device__ __forceinline__ int pack_h2(float v) {
    unsigned hb = (unsigned)__half_as_ushort(__float2half_rn(v));
    return (int)(hb | (hb << 16));
}

__global__ void k_scatterpad(const int* __restrict__ rows,
                             const int* __restrict__ cols,
                             const float* __restrict__ vals) {
    int t = blockIdx.x * blockDim.x + threadIdx.x;
    if (t < NE / 4) {
        int4   r = __ldcs(&((const int4*)rows)[t]);
        int4   c = __ldcs(&((const int4*)cols)[t]);
        float4 v = __ldcs(&((const float4*)vals)[t]);
        int p0 = atomicAdd(&g_cursor[r.x], 1);   // 4 independent ATOMG chains
        int p1 = atomicAdd(&g_cursor[r.y], 1);
        int p2 = atomicAdd(&g_cursor[r.z], 1);
        int p3 = atomicAdd(&g_cursor[r.w], 1);
        g_edges[p0] = make_int2(c.x, pack_h2(v.x));
        g_edges[p1] = make_int2(c.y, pack_h2(v.y));
        g_edges[p2] = make_int2(c.z, pack_h2(v.z));
        g_edges[p3] = make_int2(c.w, pack_h2(v.w));
    } else if (t - NE / 4 < NNODES) {
        int i = t - NE / 4;
        int c = g_counts[i];
        int pc = (c + 3) & ~3;
        int base = g_rowstart[i];
        for (int j = c; j < pc; j++) g_edges[base + j] = make_int2(0, 0);
    }
}

// ---------------- SpMM core: warp = 4 groups x 8 lanes; LDG.128 gathers 4 rows ----------
// Pure fp16 inner loop (fma.rn.f16x2), flushed to packed f32x2 accumulators.
#define HFMA2ACC(acc, xbits, vbits)                                             \
    asm("fma.rn.f16x2 %0, %1, %2, %0;" : "+r"(acc) : "r"(xbits), "r"(vbits))

#define FLUSH1(s, h)                                                            \
    asm("{\n\t"                                                                 \
        ".reg .b16 a, b;\n\t"                                                   \
        ".reg .f32 f0, f1;\n\t"                                                 \
        ".reg .b64 d;\n\t"                                                      \
        "mov.b32 {a, b}, %1;\n\t"                                               \
        "cvt.f32.f16 f0, a;\n\t"                                                \
        "cvt.f32.f16 f1, b;\n\t"                                                \
        "mov.b64 d, {f0, f1};\n\t"                                              \
        "add.rn.f32x2 %0, %0, d;\n\t"                                           \
        "}" : "+l"(s) : "r"(h))

#define FLUSHALL()                                                              \
    { FLUSH1(sA, h0); FLUSH1(sB, h1); FLUSH1(sC, h2); FLUSH1(sD, h3);           \
      h0 = h1 = h2 = h3 = 0u; }

#define ACC8H(xi, vv)                                                           \
    { HFMA2ACC(h0, (unsigned)(xi).x, vv); HFMA2ACC(h1, (unsigned)(xi).y, vv);   \
      HFMA2ACC(h2, (unsigned)(xi).z, vv); HFMA2ACC(h3, (unsigned)(xi).w, vv); }

#define REDUCE_XGROUP()                                                         \
    {                                                                           \
        _Pragma("unroll")                                                       \
        for (int off = 8; off <= 16; off <<= 1) {                               \
            s0.x += __shfl_xor_sync(0xffffffffu, s0.x, off);                    \
            s0.y += __shfl_xor_sync(0xffffffffu, s0.y, off);                    \
            s1.x += __shfl_xor_sync(0xffffffffu, s1.x, off);                    \
            s1.y += __shfl_xor_sync(0xffffffffu, s1.y, off);                    \
            s2.x += __shfl_xor_sync(0xffffffffu, s2.x, off);                    \
            s2.y += __shfl_xor_sync(0xffffffffu, s2.y, off);                    \
            s3.x += __shfl_xor_sync(0xffffffffu, s3.x, off);                    \
            s3.y += __shfl_xor_sync(0xffffffffu, s3.y, off);                    \
        }                                                                       \
    }

// fp16 chunked accumulation: flush every 4 iterations (8 edges/group) + at end.
#define ROW_SPMM(Eb, Xb, pc)                                                    \
    unsigned long long sA = 0, sB = 0, sC = 0, sD = 0;                          \
    unsigned h0 = 0, h1 = 0, h2 = 0, h3 = 0;                                    \
    unsigned kb = (unsigned)(k << 4);                                           \
    int it = 0;                                                                 \
    for (; it + 8 <= pc; it += 8) {                                             \
        int2 ea = *(const int2*)(Eb + ((unsigned)it << 3));                     \
        int2 eb = *(const int2*)(Eb + ((unsigned)(it + 4) << 3));               \
        int4 xa = *(const int4*)(Xb + (((unsigned)ea.x << 7) + kb));            \
        int4 xb = *(const int4*)(Xb + (((unsigned)eb.x << 7) + kb));            \
        unsigned va = (unsigned)ea.y, vb = (unsigned)eb.y;                      \
        ACC8H(xa, va);                                                          \
        ACC8H(xb, vb);                                                          \
        if ((it & 24) == 24) FLUSHALL();  /* it=24,56,88,... every 4 iters */   \
    }                                                                           \
    if (it < pc) {                                                              \
        int2 ea = *(const int2*)(Eb + ((unsigned)it << 3));                     \
        int4 xa = *(const int4*)(Xb + (((unsigned)ea.x << 7) + kb));            \
        unsigned va = (unsigned)ea.y;                                           \
        ACC8H(xa, va);                                                          \
    }                                                                           \
    FLUSHALL();                                                                 \
    float2 s0, s1, s2, s3;                                                      \
    asm("mov.b64 {%0, %1}, %2;" : "=f"(s0.x), "=f"(s0.y) : "l"(sA));            \
    asm("mov.b64 {%0, %1}, %2;" : "=f"(s1.x), "=f"(s1.y) : "l"(sB));            \
    asm("mov.b64 {%0, %1}, %2;" : "=f"(s2.x), "=f"(s2.y) : "l"(sC));            \
    asm("mov.b64 {%0, %1}, %2;" : "=f"(s3.x), "=f"(s3.y) : "l"(sD));

__global__ void __launch_bounds__(256, 7) k_spmm(const int4* __restrict__ X,
                                                 int4* __restrict__ Xout,
                                                 float4* __restrict__ f32out) {
    int gw = blockIdx.x * 8 + (threadIdx.x >> 5);
    if (gw >= NNODES) return;
    int lane = threadIdx.x & 31;
    int g = lane >> 3, k = lane & 7;

    int base = g_rowstart[gw];
    int pc   = (g_counts[gw] + 3) & ~3;
    const char* Eb = (const char*)(g_edges + base + g);
    const char* Xb = (const char*)X;

    ROW_SPMM(Eb, Xb, pc);
    REDUCE_XGROUP();

    if (g == 0) {
        __half2 o0 = __float22half2_rn(s0);
        __half2 o1 = __float22half2_rn(s1);
        __half2 o2 = __float22half2_rn(s2);
        __half2 o3 = __float22half2_rn(s3);
        int4 o;
        o.x = *(int*)&o0; o.y = *(int*)&o1; o.z = *(int*)&o2; o.w = *(int*)&o3;
        Xout[(size_t)gw * 8 + k] = o;
        if (g_flag[gw]) {
            __stcs(&f32out[(size_t)gw * 16 + 2 * k],     make_float4(s0.x, s0.y, s1.x, s1.y));
            __stcs(&f32out[(size_t)gw * 16 + 2 * k + 1], make_float4(s2.x, s2.y, s3.x, s3.y));
        }
    }
}

// ---------------- fused layer 3 + output assembly (12288 rows) ----------------
__global__ void __launch_bounds__(256) k_final(const int* __restrict__ users,
                                               const int* __restrict__ pos,
                                               const int* __restrict__ neg,
                                               const int4* __restrict__ X2,
                                               const float* __restrict__ user_emb,
                                               const float* __restrict__ item_emb,
                                               float* __restrict__ out) {
    int w = blockIdx.x * 8 + (threadIdx.x >> 5);
    if (w >= 3 * BATCH) return;
    int lane = threadIdx.x & 31;
    int g = lane >> 3, k = lane & 7;
    int kk = w / BATCH;
    int b = w - kk * BATCH;
    int row = (kk == 0) ? users[b] : (N_USERS + ((kk == 1) ? pos[b] : neg[b]));

    int base = g_rowstart[row];
    int pc   = (g_counts[row] + 3) & ~3;
    const char* Eb = (const char*)(g_edges + base + g);
    const char* Xb = (const char*)X2;

    ROW_SPMM(Eb, Xb, pc);
    REDUCE_XGROUP();

    if (g == 0) {
        const float4* e0p = (row < N_USERS)
            ? (const float4*)user_emb + (size_t)row * 16
            : (const float4*)item_emb + (size_t)(row - N_USERS) * 16;
        float4 ea = e0p[2 * k],               eb = e0p[2 * k + 1];
        float4 l1a = g_l1f[(size_t)row * 16 + 2 * k], l1b = g_l1f[(size_t)row * 16 + 2 * k + 1];
        float4 l2a = g_l2f[(size_t)row * 16 + 2 * k], l2b = g_l2f[(size_t)row * 16 + 2 * k + 1];
        float4 ra, rb;
        ra.x = (ea.x + l1a.x + l2a.x + s0.x) * 0.25f;
        ra.y = (ea.y + l1a.y + l2a.y + s0.y) * 0.25f;
        ra.z = (ea.z + l1a.z + l2a.z + s1.x) * 0.25f;
        ra.w = (ea.w + l1a.w + l2a.w + s1.y) * 0.25f;
        rb.x = (eb.x + l1b.x + l2b.x + s2.x) * 0.25f;
        rb.y = (eb.y + l1b.y + l2b.y + s2.y) * 0.25f;
        rb.z = (eb.z + l1b.z + l2b.z + s3.x) * 0.25f;
        rb.w = (eb.w + l1b.w + l2b.w + s3.y) * 0.25f;
        ((float4*)out)[(size_t)w * 16 + 2 * k]     = ra;
        ((float4*)out)[(size_t)w * 16 + 2 * k + 1] = rb;
    }
}

// ---------------- launch ----------------
extern "C" void kernel_launch(void* const* d_in, const int* in_sizes, int n_in,
                              void* d_out, int out_size) {
    const float* user_emb = (const float*)d_in[0];
    const float* item_emb = (const float*)d_in[1];
    const float* adj_vals = (const float*)d_in[2];
    const int*   adj_rows = (const int*)d_in[3];
    const int*   adj_cols = (const int*)d_in[4];
    const int*   users    = (const int*)d_in[5];
    const int*   pos      = (const int*)d_in[6];
    const int*   neg      = (const int*)d_in[7];
    float* out = (float*)d_out;

    void *p_xa, *p_xb, *p_l1, *p_l2, *p_cnt, *p_flag, *p_ss;
    cudaGetSymbolAddress(&p_xa, g_xa);
    cudaGetSymbolAddress(&p_xb, g_xb);
    cudaGetSymbolAddress(&p_l1, g_l1f);
    cudaGetSymbolAddress(&p_l2, g_l2f);
    cudaGetSymbolAddress(&p_cnt, g_counts);
    cudaGetSymbolAddress(&p_flag, g_flag);
    cudaGetSymbolAddress(&p_ss, g_ss);

    const int T = 256;

    // zeroing via memset (graph-capturable, no kernel launch)
    cudaMemsetAsync(p_cnt, 0, NNODES * sizeof(int), 0);
    cudaMemsetAsync(p_flag, 0, NNODES, 0);
    cudaMemsetAsync(p_ss, 0, NB * sizeof(unsigned long long), 0);

    // 1: count(x4) + fp16 init + flags  (2.4M threads covers all index spaces)
    int ciThreads = NNODES * 8;
    k_countinit<<<(ciThreads + T - 1) / T, T>>>(adj_rows, user_emb, item_emb, users, pos, neg);
    // 2: single-pass scan
    k_scanLB<<<NB, 1024>>>();
    // 3: scatter(x4) + pad
    int scThreads = NE / 4 + NNODES;
    k_scatterpad<<<(scThreads + T - 1) / T, T>>>(adj_rows, adj_cols, adj_vals);

    // 4,5: propagation layers 1 and 2  (layer-1 spmm is the 4th kernel -> profiled)
    int spmmBlocks = (NNODES + 7) / 8;
    k_spmm<<<spmmBlocks, 256>>>((const int4*)p_xa, (int4*)p_xb, (float4*)p_l1);
    k_spmm<<<spmmBlocks, 256>>>((const int4*)p_xb, (int4*)p_xa, (float4*)p_l2);

    // 6: layer 3 at sampled rows + output assembly
    int finBlocks = (3 * BATCH + 7) / 8;
    k_final<<<finBlocks, 256>>>(users, pos, neg, (const int4*)p_xa,
                                user_emb, item_emb, out);
}

// round 8
// speedup vs baseline: 1.1776x; 1.1776x over previous
#include <cuda_runtime.h>
#include <cuda_fp16.h>

#define N_USERS 200000
#define N_ITEMS 100000
#define NNODES  300000
#define NE      5000000
#define BATCH   4096
#define NEPAD   (NE + 3 * NNODES + 16)
#define NB      ((NNODES + 1023) / 1024)

// ---------------- scratch (static device globals; no allocation) ----------------
__device__ int4   g_xa[(size_t)NNODES * 8];      // fp16 features ping (8 halves per int4)
__device__ int4   g_xb[(size_t)NNODES * 8];      // fp16 features pong
__device__ float4 g_l1f[(size_t)NNODES * 16];    // fp32 layer-1 rows (flagged only)
__device__ float4 g_l2f[(size_t)NNODES * 16];    // fp32 layer-2 rows (flagged only)
__device__ int    g_rowstart[NNODES];
__device__ int    g_counts[NNODES];
__device__ int    g_cursor[NNODES];
__device__ char   g_flag[NNODES];                // sampled rows (need fp32 l1/l2)
__device__ char   g_mark[NNODES];                // rows needing layer-2 output
__device__ int    g_mlist[NNODES];
__device__ int    g_nmark;
__device__ unsigned long long g_ss[NB];          // lookback scan status: (sum<<2)|state
__device__ __align__(16) int2 g_edges[NEPAD];    // (col, bits(val)), row-sorted, 4-padded

// ---------------- 1: count (x4 unrolled) + E0 fp16 init + sample flags ----------------
__global__ void k_countinit(const int* __restrict__ rows,
                            const float* __restrict__ user_emb,
                            const float* __restrict__ item_emb,
                            const int* __restrict__ users,
                            const int* __restrict__ pos,
                            const int* __restrict__ neg) {
    int t = blockIdx.x * blockDim.x + threadIdx.x;
    if (t < NE / 4) {
        int4 r = __ldcs(&((const int4*)rows)[t]);
        atomicAdd(&g_counts[r.x], 1);            // result unused -> REDG (fire & forget)
        atomicAdd(&g_counts[r.y], 1);
        atomicAdd(&g_counts[r.z], 1);
        atomicAdd(&g_counts[r.w], 1);
    }
    if (t < NNODES * 8) {
        int node = t >> 3, k = t & 7;
        const float4* src = (node < N_USERS)
            ? (const float4*)user_emb + (size_t)node * 16
            : (const float4*)item_emb + (size_t)(node - N_USERS) * 16;
        float4 a = __ldcs(&src[2 * k]);
        float4 b = __ldcs(&src[2 * k + 1]);
        __half2 h0 = __floats2half2_rn(a.x, a.y);
        __half2 h1 = __floats2half2_rn(a.z, a.w);
        __half2 h2 = __floats2half2_rn(b.x, b.y);
        __half2 h3 = __floats2half2_rn(b.z, b.w);
        int4 o;
        o.x = *(int*)&h0; o.y = *(int*)&h1; o.z = *(int*)&h2; o.w = *(int*)&h3;
        g_xa[t] = o;
    }
    if (t < BATCH) {
        int u = users[t], p = N_USERS + pos[t], n = N_USERS + neg[t];
        g_flag[u] = 1; g_flag[p] = 1; g_flag[n] = 1;
        g_mark[u] = 1; g_mark[p] = 1; g_mark[n] = 1;   // sampled rows need l2 too
    }
}

// ---------------- 2: single-pass decoupled-lookback scan of padded counts ----------------
__global__ void __launch_bounds__(1024) k_scanLB() {
    __shared__ int sh[1024];
    __shared__ int s_prefix;
    int tid = threadIdx.x, b = blockIdx.x;
    int i = b * 1024 + tid;
    int c = (i < NNODES) ? g_counts[i] : 0;
    int v = (c + 3) & ~3;                      // pad rows to multiple of 4 edges
    sh[tid] = v;
    __syncthreads();
    #pragma unroll
    for (int off = 1; off < 1024; off <<= 1) {
        int t = (tid >= off) ? sh[tid - off] : 0;
        __syncthreads();
        sh[tid] += t;
        __syncthreads();
    }
    int incl = sh[tid];
    int total = sh[1023];
    if (tid == 0) {
        if (b == 0) {
            atomicExch(&g_ss[0], ((unsigned long long)(unsigned)total << 2) | 2ull);
            s_prefix = 0;
        } else {
            atomicExch(&g_ss[b], ((unsigned long long)(unsigned)total << 2) | 1ull);
            int run = 0;
            for (int p = b - 1; ; p--) {
                unsigned long long s;
                do { s = atomicOr(&g_ss[p], 0ull); } while (!(s & 3ull));
                run += (int)(s >> 2);
                if ((s & 3ull) == 2ull) break;
            }
            atomicExch(&g_ss[b], ((unsigned long long)(unsigned)(run + total) << 2) | 2ull);
            s_prefix = run;
        }
    }
    __syncthreads();
    if (i < NNODES) {
        int excl = s_prefix + incl - v;
        g_rowstart[i] = excl;
        g_cursor[i]   = excl;
    }
}

// ---------------- 3: scatter (x4, MLP=4) + 2-hop marking + padding ----------------
__global__ void k_scatterpad(const int* __restrict__ rows,
                             const int* __restrict__ cols,
                             const float* __restrict__ vals) {
    int t = blockIdx.x * blockDim.x + threadIdx.x;
    if (t < NE / 4) {
        int4   r = __ldcs(&((const int4*)rows)[t]);
        int4   c = __ldcs(&((const int4*)cols)[t]);
        float4 v = __ldcs(&((const float4*)vals)[t]);
        int p0 = atomicAdd(&g_cursor[r.x], 1);   // 4 independent ATOMG chains
        int p1 = atomicAdd(&g_cursor[r.y], 1);
        int p2 = atomicAdd(&g_cursor[r.z], 1);
        int p3 = atomicAdd(&g_cursor[r.w], 1);
        g_edges[p0] = make_int2(c.x, __float_as_int(v.x));
        g_edges[p1] = make_int2(c.y, __float_as_int(v.y));
        g_edges[p2] = make_int2(c.z, __float_as_int(v.z));
        g_edges[p3] = make_int2(c.w, __float_as_int(v.w));
        // 2-hop marking: columns of flagged rows need layer-2 output
        if (g_flag[r.x]) g_mark[c.x] = 1;
        if (g_flag[r.y]) g_mark[c.y] = 1;
        if (g_flag[r.z]) g_mark[c.z] = 1;
        if (g_flag[r.w]) g_mark[c.w] = 1;
    } else if (t - NE / 4 < NNODES) {
        int i = t - NE / 4;
        int c = g_counts[i];
        int pc = (c + 3) & ~3;
        int base = g_rowstart[i];
        for (int j = c; j < pc; j++) g_edges[base + j] = make_int2(0, 0);
    }
}

// ---------------- compaction of marked rows (warp-aggregated atomic) ----------------
__global__ void k_compact() {
    int i = blockIdx.x * blockDim.x + threadIdx.x;
    bool m = (i < NNODES) && g_mark[i];
    unsigned ballot = __ballot_sync(0xffffffffu, m);
    int cnt = __popc(ballot);
    int base = 0;
    if ((threadIdx.x & 31) == 0 && cnt) base = atomicAdd(&g_nmark, cnt);
    base = __shfl_sync(0xffffffffu, base, 0);
    if (m) {
        int off = __popc(ballot & ((1u << (threadIdx.x & 31)) - 1u));
        g_mlist[base + off] = i;
    }
}

// ---------------- SpMM core (R6 FFMA2 form): warp = 4 groups x 8 lanes ----------------
#define FMA2(acc, h2bits, vv2)                                                  \
    asm("{\n\t"                                                                 \
        ".reg .b16 h0, h1;\n\t"                                                 \
        ".reg .f32 f0, f1;\n\t"                                                 \
        ".reg .b64 d;\n\t"                                                      \
        "mov.b32 {h0, h1}, %1;\n\t"                                             \
        "cvt.f32.f16 f0, h0;\n\t"                                               \
        "cvt.f32.f16 f1, h1;\n\t"                                               \
        "mov.b64 d, {f0, f1};\n\t"                                              \
        "fma.rn.f32x2 %0, d, %2, %0;\n\t"                                       \
        "}" : "+l"(acc) : "r"(h2bits), "l"(vv2))

#define PACK2(dst, v) asm("mov.b64 %0, {%1, %1};" : "=l"(dst) : "f"(v))

#define ACC8(xi, vv2)                                                           \
    { FMA2(sA, (xi).x, vv2); FMA2(sB, (xi).y, vv2);                             \
      FMA2(sC, (xi).z, vv2); FMA2(sD, (xi).w, vv2); }

#define REDUCE_XGROUP()                                                         \
    {                                                                           \
        _Pragma("unroll")                                                       \
        for (int off = 8; off <= 16; off <<= 1) {                               \
            s0.x += __shfl_xor_sync(0xffffffffu, s0.x, off);                    \
            s0.y += __shfl_xor_sync(0xffffffffu, s0.y, off);                    \
            s1.x += __shfl_xor_sync(0xffffffffu, s1.x, off);                    \
            s1.y += __shfl_xor_sync(0xffffffffu, s1.y, off);                    \
            s2.x += __shfl_xor_sync(0xffffffffu, s2.x, off);                    \
            s2.y += __shfl_xor_sync(0xffffffffu, s2.y, off);                    \
            s3.x += __shfl_xor_sync(0xffffffffu, s3.x, off);                    \
            s3.y += __shfl_xor_sync(0xffffffffu, s3.y, off);                    \
        }                                                                       \
    }

#define ROW_SPMM(Eb, Xb, pc)                                                    \
    unsigned long long sA = 0, sB = 0, sC = 0, sD = 0;                          \
    unsigned kb = (unsigned)(k << 4);                                           \
    int it = 0;                                                                 \
    for (; it + 8 <= pc; it += 8) {                                             \
        int2 ea = *(const int2*)(Eb + ((unsigned)it << 3));                     \
        int2 eb = *(const int2*)(Eb + ((unsigned)(it + 4) << 3));               \
        int4 xa = *(const int4*)(Xb + (((unsigned)ea.x << 7) + kb));            \
        int4 xb = *(const int4*)(Xb + (((unsigned)eb.x << 7) + kb));            \
        unsigned long long va2, vb2;                                            \
        PACK2(va2, __int_as_float(ea.y));                                       \
        PACK2(vb2, __int_as_float(eb.y));                                       \
        ACC8(xa, va2);                                                          \
        ACC8(xb, vb2);                                                          \
    }                                                                           \
    if (it < pc) {                                                              \
        int2 ea = *(const int2*)(Eb + ((unsigned)it << 3));                     \
        int4 xa = *(const int4*)(Xb + (((unsigned)ea.x << 7) + kb));            \
        unsigned long long va2;                                                 \
        PACK2(va2, __int_as_float(ea.y));                                       \
        ACC8(xa, va2);                                                          \
    }                                                                           \
    float2 s0, s1, s2, s3;                                                      \
    asm("mov.b64 {%0, %1}, %2;" : "=f"(s0.x), "=f"(s0.y) : "l"(sA));            \
    asm("mov.b64 {%0, %1}, %2;" : "=f"(s1.x), "=f"(s1.y) : "l"(sB));            \
    asm("mov.b64 {%0, %1}, %2;" : "=f"(s2.x), "=f"(s2.y) : "l"(sC));            \
    asm("mov.b64 {%0, %1}, %2;" : "=f"(s3.x), "=f"(s3.y) : "l"(sD));

__device__ __forceinline__ void spmm_row(int gw, int g, int k,
                                         const char* __restrict__ Xb,
                                         int4* __restrict__ Xout,
                                         float4* __restrict__ f32out) {
    int base = g_rowstart[gw];
    int pc   = (g_counts[gw] + 3) & ~3;
    const char* Eb = (const char*)(g_edges + base + g);

    ROW_SPMM(Eb, Xb, pc);
    REDUCE_XGROUP();

    if (g == 0) {
        __half2 h0 = __float22half2_rn(s0);
        __half2 h1 = __float22half2_rn(s1);
        __half2 h2 = __float22half2_rn(s2);
        __half2 h3 = __float22half2_rn(s3);
        int4 o;
        o.x = *(int*)&h0; o.y = *(int*)&h1; o.z = *(int*)&h2; o.w = *(int*)&h3;
        Xout[(size_t)gw * 8 + k] = o;
        if (g_flag[gw]) {
            __stcs(&f32out[(size_t)gw * 16 + 2 * k],     make_float4(s0.x, s0.y, s1.x, s1.y));
            __stcs(&f32out[(size_t)gw * 16 + 2 * k + 1], make_float4(s2.x, s2.y, s3.x, s3.y));
        }
    }
}

// layer 1: all rows
__global__ void __launch_bounds__(256, 8) k_spmm(const int4* __restrict__ X,
                                                 int4* __restrict__ Xout,
                                                 float4* __restrict__ f32out) {
    int gw = blockIdx.x * 8 + (threadIdx.x >> 5);
    if (gw >= NNODES) return;
    int lane = threadIdx.x & 31;
    spmm_row(gw, lane >> 3, lane & 7, (const char*)X, Xout, f32out);
}

// layer 2: only marked rows (grid-strided over compacted list)
__global__ void __launch_bounds__(256, 8) k_spmm2(const int4* __restrict__ X,
                                                  int4* __restrict__ Xout,
                                                  float4* __restrict__ f32out) {
    int nm = g_nmark;
    int lane = threadIdx.x & 31;
    int g = lane >> 3, k = lane & 7;
    int stride = gridDim.x * 8;
    for (int w = blockIdx.x * 8 + (threadIdx.x >> 5); w < nm; w += stride) {
        int gw = g_mlist[w];
        spmm_row(gw, g, k, (const char*)X, Xout, f32out);
    }
}

// ---------------- fused layer 3 + output assembly (12288 rows) ----------------
__global__ void __launch_bounds__(256) k_final(const int* __restrict__ users,
                                               const int* __restrict__ pos,
                                               const int* __restrict__ neg,
                                               const int4* __restrict__ X2,
                                               const float* __restrict__ user_emb,
                                               const float* __restrict__ item_emb,
                                               float* __restrict__ out) {
    int w = blockIdx.x * 8 + (threadIdx.x >> 5);
    if (w >= 3 * BATCH) return;
    int lane = threadIdx.x & 31;
    int g = lane >> 3, k = lane & 7;
    int kk = w / BATCH;
    int b = w - kk * BATCH;
    int row = (kk == 0) ? users[b] : (N_USERS + ((kk == 1) ? pos[b] : neg[b]));

    int base = g_rowstart[row];
    int pc   = (g_counts[row] + 3) & ~3;
    const char* Eb = (const char*)(g_edges + base + g);
    const char* Xb = (const char*)X2;

    ROW_SPMM(Eb, Xb, pc);
    REDUCE_XGROUP();

    if (g == 0) {
        const float4* e0p = (row < N_USERS)
            ? (const float4*)user_emb + (size_t)row * 16
            : (const float4*)item_emb + (size_t)(row - N_USERS) * 16;
        float4 ea = e0p[2 * k],               eb = e0p[2 * k + 1];
        float4 l1a = g_l1f[(size_t)row * 16 + 2 * k], l1b = g_l1f[(size_t)row * 16 + 2 * k + 1];
        float4 l2a = g_l2f[(size_t)row * 16 + 2 * k], l2b = g_l2f[(size_t)row * 16 + 2 * k + 1];
        float4 ra, rb;
        ra.x = (ea.x + l1a.x + l2a.x + s0.x) * 0.25f;
        ra.y = (ea.y + l1a.y + l2a.y + s0.y) * 0.25f;
        ra.z = (ea.z + l1a.z + l2a.z + s1.x) * 0.25f;
        ra.w = (ea.w + l1a.w + l2a.w + s1.y) * 0.25f;
        rb.x = (eb.x + l1b.x + l2b.x + s2.x) * 0.25f;
        rb.y = (eb.y + l1b.y + l2b.y + s2.y) * 0.25f;
        rb.z = (eb.z + l1b.z + l2b.z + s3.x) * 0.25f;
        rb.w = (eb.w + l1b.w + l2b.w + s3.y) * 0.25f;
        ((float4*)out)[(size_t)w * 16 + 2 * k]     = ra;
        ((float4*)out)[(size_t)w * 16 + 2 * k + 1] = rb;
    }
}

// ---------------- launch ----------------
extern "C" void kernel_launch(void* const* d_in, const int* in_sizes, int n_in,
                              void* d_out, int out_size) {
    const float* user_emb = (const float*)d_in[0];
    const float* item_emb = (const float*)d_in[1];
    const float* adj_vals = (const float*)d_in[2];
    const int*   adj_rows = (const int*)d_in[3];
    const int*   adj_cols = (const int*)d_in[4];
    const int*   users    = (const int*)d_in[5];
    const int*   pos      = (const int*)d_in[6];
    const int*   neg      = (const int*)d_in[7];
    float* out = (float*)d_out;

    void *p_xa, *p_xb, *p_l1, *p_l2, *p_cnt, *p_flag, *p_mark, *p_nmark, *p_ss;
    cudaGetSymbolAddress(&p_xa, g_xa);
    cudaGetSymbolAddress(&p_xb, g_xb);
    cudaGetSymbolAddress(&p_l1, g_l1f);
    cudaGetSymbolAddress(&p_l2, g_l2f);
    cudaGetSymbolAddress(&p_cnt, g_counts);
    cudaGetSymbolAddress(&p_flag, g_flag);
    cudaGetSymbolAddress(&p_mark, g_mark);
    cudaGetSymbolAddress(&p_nmark, g_nmark);
    cudaGetSymbolAddress(&p_ss, g_ss);

    const int T = 256;

    // zeroing via memset (graph-capturable, no kernel launch)
    cudaMemsetAsync(p_cnt, 0, NNODES * sizeof(int), 0);
    cudaMemsetAsync(p_flag, 0, NNODES, 0);
    cudaMemsetAsync(p_mark, 0, NNODES, 0);
    cudaMemsetAsync(p_nmark, 0, sizeof(int), 0);
    cudaMemsetAsync(p_ss, 0, NB * sizeof(unsigned long long), 0);

    // 1: count(x4) + fp16 init + flags
    int ciThreads = NNODES * 8;
    k_countinit<<<(ciThreads + T - 1) / T, T>>>(adj_rows, user_emb, item_emb, users, pos, neg);
    // 2: single-pass scan
    k_scanLB<<<NB, 1024>>>();
    // 3: scatter(x4) + 2-hop mark + pad
    int scThreads = NE / 4 + NNODES;
    k_scatterpad<<<(scThreads + T - 1) / T, T>>>(adj_rows, adj_cols, adj_vals);

    // 4: layer 1 over all nodes (4th kernel -> profiled)
    int spmmBlocks = (NNODES + 7) / 8;
    k_spmm<<<spmmBlocks, 256>>>((const int4*)p_xa, (int4*)p_xb, (float4*)p_l1);

    // 5: compact marked rows
    k_compact<<<(NNODES + T - 1) / T, T>>>();

    // 6: layer 2 over marked rows only
    k_spmm2<<<2048, 256>>>((const int4*)p_xb, (int4*)p_xa, (float4*)p_l2);

    // 7: layer 3 at sampled rows + output assembly
    int finBlocks = (3 * BATCH + 7) / 8;
    k_final<<<finBlocks, 256>>>(users, pos, neg, (const int4*)p_xa,
                                user_emb, item_emb, out);
}